// round 3
// baseline (speedup 1.0000x reference)
#include <cuda_runtime.h>
#include <math.h>

#define Bn   64
#define Sn   128
#define Vn   32000
#define En   256
#define EHn  512
#define Hn   512
#define An   256
#define KFC  1280   // H + Eh + E
#define G3   1536   // 3*H

// ---- scratch (allocation-free: __device__ globals) ----
__device__ float g_embedded[Bn*En];
__device__ float g_dproj[Bn*An];
__device__ float g_scores[Bn*Sn];
__device__ float g_context[Bn*EHn];
__device__ float g_gx[Bn*G3];
__device__ float g_gh[Bn*G3];
__device__ float g_act[Bn*KFC];   // [new_hidden(512) | context(512) | embedded(256)]

// ============================================================
// K0: embedded = emb[tgt];  dproj = hidden @ Wa_dec + ba
// grid 64 (b), 256 threads (a / e index)
// ============================================================
__global__ void k0_embed_dproj(const int* __restrict__ tgt,
                               const float* __restrict__ hidden,
                               const float* __restrict__ emb,
                               const float* __restrict__ Wa_dec,
                               const float* __restrict__ ba) {
    int b = blockIdx.x;
    int a = threadIdx.x;
    __shared__ float h_s[Hn];
    for (int i = threadIdx.x; i < Hn; i += 256) h_s[i] = hidden[b*Hn + i];

    int tok = tgt[b];
    float ev = emb[(size_t)tok*En + a];
    g_embedded[b*En + a] = ev;
    g_act[b*KFC + Hn + EHn + a] = ev;   // embedded at offset 1024
    __syncthreads();

    float acc = ba[a];
    #pragma unroll 8
    for (int h = 0; h < Hn; h++) acc += h_s[h] * Wa_dec[h*An + a];
    g_dproj[b*An + a] = acc;
}

// ============================================================
// K1: energy = tanh(enc @ Wa_enc + dproj + ba);  scores = energy . v_att
// grid (2 s-chunks, 64 b), 256 threads.  Thread tile: 8 s x 8 a.
// ============================================================
__global__ __launch_bounds__(256, 1)
void k1_energy(const float* __restrict__ enc,
               const float* __restrict__ Wa_enc,
               const float* __restrict__ v_att,
               const int* __restrict__ mask) {
    int b  = blockIdx.y;
    int s0 = blockIdx.x * 64;
    int ta = threadIdx.x & 31;    // lane: a-tile
    int ts = threadIdx.x >> 5;    // warp: s-tile

    __shared__ float w_s[32][An];     // [e_chunk][a]
    __shared__ float e_s[32][68];     // [e_chunk][s]

    float acc[8][8] = {};

    for (int e0 = 0; e0 < EHn; e0 += 32) {
        for (int i = threadIdx.x; i < 32*An; i += 256) {
            int er = i >> 8, a = i & 255;
            w_s[er][a] = Wa_enc[(e0 + er)*An + a];
        }
        for (int i = threadIdx.x; i < 64*32; i += 256) {
            int s = i >> 5, er = i & 31;
            e_s[er][s] = enc[((size_t)(b*Sn + s0 + s))*EHn + e0 + er];
        }
        __syncthreads();

        #pragma unroll
        for (int er = 0; er < 32; er++) {
            float4 w0 = *(const float4*)&w_s[er][ta*4];
            float4 w1 = *(const float4*)&w_s[er][128 + ta*4];
            float4 ea = *(const float4*)&e_s[er][ts*8];
            float4 eb = *(const float4*)&e_s[er][ts*8 + 4];
            float ev[8] = {ea.x, ea.y, ea.z, ea.w, eb.x, eb.y, eb.z, eb.w};
            #pragma unroll
            for (int j = 0; j < 8; j++) {
                acc[j][0] += ev[j]*w0.x; acc[j][1] += ev[j]*w0.y;
                acc[j][2] += ev[j]*w0.z; acc[j][3] += ev[j]*w0.w;
                acc[j][4] += ev[j]*w1.x; acc[j][5] += ev[j]*w1.y;
                acc[j][6] += ev[j]*w1.z; acc[j][7] += ev[j]*w1.w;
            }
        }
        __syncthreads();
    }

    // epilogue: tanh(+dproj) . v_att, reduce over a (whole warp covers all 256 a)
    float dp[8], va[8];
    #pragma unroll
    for (int c = 0; c < 4; c++) {
        dp[c]   = g_dproj[b*An + ta*4 + c];
        dp[c+4] = g_dproj[b*An + 128 + ta*4 + c];
        va[c]   = v_att[ta*4 + c];
        va[c+4] = v_att[128 + ta*4 + c];
    }
    #pragma unroll
    for (int j = 0; j < 8; j++) {
        float p = 0.f;
        #pragma unroll
        for (int c = 0; c < 8; c++) p += tanhf(acc[j][c] + dp[c]) * va[c];
        #pragma unroll
        for (int o = 16; o > 0; o >>= 1) p += __shfl_xor_sync(0xffffffffu, p, o);
        if (ta == 0) {
            int s = s0 + ts*8 + j;
            g_scores[b*Sn + s] = mask[b*Sn + s] ? p : -1e9f;
        }
    }
}

// ============================================================
// K2: softmax over S, context = attn @ enc.  grid 64 (b), 128 threads.
// ============================================================
__global__ void k2_softmax_ctx(const float* __restrict__ enc,
                               float* __restrict__ out_attn) {
    int b = blockIdx.x;
    int t = threadIdx.x;  // 128 = Sn
    __shared__ float at_s[Sn];
    __shared__ float red[4];

    float v = g_scores[b*Sn + t];
    float m = v;
    #pragma unroll
    for (int o = 16; o > 0; o >>= 1) m = fmaxf(m, __shfl_xor_sync(0xffffffffu, m, o));
    if ((t & 31) == 0) red[t >> 5] = m;
    __syncthreads();
    m = fmaxf(fmaxf(red[0], red[1]), fmaxf(red[2], red[3]));
    __syncthreads();

    float ex = __expf(v - m);
    float sm = ex;
    #pragma unroll
    for (int o = 16; o > 0; o >>= 1) sm += __shfl_xor_sync(0xffffffffu, sm, o);
    if ((t & 31) == 0) red[t >> 5] = sm;
    __syncthreads();
    float tot = red[0] + red[1] + red[2] + red[3];

    float at = ex / tot;
    at_s[t] = at;
    if (out_attn) out_attn[b*Sn + t] = at;
    __syncthreads();

    for (int h = t; h < EHn; h += 128) {
        float c = 0.f;
        #pragma unroll 8
        for (int s = 0; s < Sn; s++) c += at_s[s] * enc[((size_t)(b*Sn + s))*EHn + h];
        g_context[b*EHn + h] = c;
        g_act[b*KFC + Hn + h] = c;   // context at offset 512
    }
}

// ============================================================
// K3: gx = x @ W_ih^T + b_ih (x=[emb|ctx], K=768); gh = hidden @ W_hh^T + b_hh (K=512)
// grid (48 j-tiles, 2 b-halves), 256 thr
// ============================================================
__global__ __launch_bounds__(256, 2)
void k3_gates(const float* __restrict__ hidden,
              const float* __restrict__ W_ih, const float* __restrict__ W_hh,
              const float* __restrict__ b_ih, const float* __restrict__ b_hh) {
    int tj = threadIdx.x & 31;
    int tb = threadIdx.x >> 5;
    int j  = blockIdx.x*32 + tj;
    int bbase = blockIdx.y * 32;

    __shared__ float xs[64][36];
    float accx[4] = {}, acch[4] = {};

    // gx: K = 768 over x = [embedded(256) | context(512)]
    for (int kc = 0; kc < 768; kc += 64) {
        for (int i = threadIdx.x; i < 64*32; i += 256) {
            int bb = i >> 6, k = i & 63;
            int kk = kc + k;
            float val = (kk < En) ? g_embedded[(bbase + bb)*En + kk]
                                  : g_context[(bbase + bb)*EHn + (kk - En)];
            xs[k][bb] = val;
        }
        __syncthreads();
        #pragma unroll 4
        for (int k4 = 0; k4 < 64; k4 += 4) {
            float4 w = *(const float4*)&W_ih[(size_t)j*768 + kc + k4];
            float wv[4] = {w.x, w.y, w.z, w.w};
            #pragma unroll
            for (int c = 0; c < 4; c++) {
                float4 a0 = *(const float4*)&xs[k4 + c][tb*4];
                accx[0] += a0.x*wv[c]; accx[1] += a0.y*wv[c];
                accx[2] += a0.z*wv[c]; accx[3] += a0.w*wv[c];
            }
        }
        __syncthreads();
    }

    // gh: K = 512 over hidden
    for (int kc = 0; kc < 512; kc += 64) {
        for (int i = threadIdx.x; i < 64*32; i += 256) {
            int bb = i >> 6, k = i & 63;
            xs[k][bb] = hidden[(bbase + bb)*Hn + kc + k];
        }
        __syncthreads();
        #pragma unroll 4
        for (int k4 = 0; k4 < 64; k4 += 4) {
            float4 w = *(const float4*)&W_hh[(size_t)j*512 + kc + k4];
            float wv[4] = {w.x, w.y, w.z, w.w};
            #pragma unroll
            for (int c = 0; c < 4; c++) {
                float4 a0 = *(const float4*)&xs[k4 + c][tb*4];
                acch[0] += a0.x*wv[c]; acch[1] += a0.y*wv[c];
                acch[2] += a0.z*wv[c]; acch[3] += a0.w*wv[c];
            }
        }
        __syncthreads();
    }

    float bi = b_ih[j], bh = b_hh[j];
    #pragma unroll
    for (int r = 0; r < 4; r++) {
        int bb = bbase + tb*4 + r;
        g_gx[bb*G3 + j] = accx[r] + bi;
        g_gh[bb*G3 + j] = acch[r] + bh;
    }
}

// ============================================================
// K3b: GRU combine -> new_hidden.  32768 threads.
// ============================================================
__global__ void k3b_gru(const float* __restrict__ hidden, float* __restrict__ out_h) {
    int gid = blockIdx.x*256 + threadIdx.x;
    int b = gid >> 9, i = gid & 511;
    const float* gx = g_gx + b*G3;
    const float* gh = g_gh + b*G3;
    float r = 1.f/(1.f + __expf(-(gx[i]        + gh[i])));
    float z = 1.f/(1.f + __expf(-(gx[Hn + i]   + gh[Hn + i])));
    float n = tanhf(gx[2*Hn + i] + r*gh[2*Hn + i]);
    float nh = (1.f - z)*n + z*hidden[b*Hn + i];
    g_act[b*KFC + i] = nh;                 // new_hidden at offset 0
    if (out_h) out_h[b*Hn + i] = nh;
}

// ============================================================
// K4: prediction = act @ W_fc + b_fc.   grid 250 (v-tiles of 128), 256 thr.
// Thread tile 8 b x 4 v; act staged [k][b] in smem (warp-broadcast LDS.128).
// ============================================================
__global__ __launch_bounds__(256, 2)
void k4_fc(const float* __restrict__ W_fc, const float* __restrict__ b_fc,
           float* __restrict__ out) {
    int tv = threadIdx.x & 31;
    int tb = threadIdx.x >> 5;
    int vb = blockIdx.x*128 + tv*4;

    __shared__ float as[128][68];
    float acc[8][4] = {};

    for (int kc = 0; kc < KFC; kc += 128) {
        for (int i = threadIdx.x; i < 128*64; i += 256) {
            int bb = i >> 7, k = i & 127;
            as[k][bb] = g_act[bb*KFC + kc + k];
        }
        __syncthreads();
        #pragma unroll 8
        for (int k = 0; k < 128; k++) {
            float4 w  = __ldg((const float4*)&W_fc[(size_t)(kc + k)*Vn + vb]);
            float4 a0 = *(const float4*)&as[k][tb*8];
            float4 a1 = *(const float4*)&as[k][tb*8 + 4];
            float av[8] = {a0.x, a0.y, a0.z, a0.w, a1.x, a1.y, a1.z, a1.w};
            #pragma unroll
            for (int r = 0; r < 8; r++) {
                acc[r][0] += av[r]*w.x; acc[r][1] += av[r]*w.y;
                acc[r][2] += av[r]*w.z; acc[r][3] += av[r]*w.w;
            }
        }
        __syncthreads();
    }

    float4 bias = *(const float4*)&b_fc[vb];
    #pragma unroll
    for (int r = 0; r < 8; r++) {
        int bb = tb*8 + r;
        float4 o;
        o.x = acc[r][0] + bias.x; o.y = acc[r][1] + bias.y;
        o.z = acc[r][2] + bias.z; o.w = acc[r][3] + bias.w;
        *(float4*)&out[(size_t)bb*Vn + vb] = o;
    }
}

// ============================================================
extern "C" void kernel_launch(void* const* d_in, const int* in_sizes, int n_in,
                              void* d_out, int out_size) {
    const int*   tgt    = (const int*)d_in[0];
    const float* hidden = (const float*)d_in[1];
    const float* enc    = (const float*)d_in[2];
    const int*   mask   = (const int*)d_in[3];     // bool -> int32 in harness
    const float* emb    = (const float*)d_in[4];
    const float* Wa_enc = (const float*)d_in[5];
    const float* Wa_dec = (const float*)d_in[6];
    const float* ba     = (const float*)d_in[7];
    const float* v_att  = (const float*)d_in[8];
    const float* W_ih   = (const float*)d_in[9];
    const float* W_hh   = (const float*)d_in[10];
    const float* b_ih   = (const float*)d_in[11];
    const float* b_hh   = (const float*)d_in[12];
    const float* W_fc   = (const float*)d_in[13];
    const float* b_fc   = (const float*)d_in[14];

    float* out_pred = (float*)d_out;
    float* out_h    = nullptr;
    float* out_attn = nullptr;
    if (out_size >= Bn*Vn + Bn*Hn + Bn*Sn) {
        out_h    = out_pred + (size_t)Bn*Vn;
        out_attn = out_h    + (size_t)Bn*Hn;
    }

    k0_embed_dproj<<<Bn, 256>>>(tgt, hidden, emb, Wa_dec, ba);
    k1_energy<<<dim3(2, Bn), 256>>>(enc, Wa_enc, v_att, mask);
    k2_softmax_ctx<<<Bn, 128>>>(enc, out_attn);
    k3_gates<<<dim3(48, 2), 256>>>(hidden, W_ih, W_hh, b_ih, b_hh);
    k3b_gru<<<128, 256>>>(hidden, out_h);
    k4_fc<<<250, 256>>>(W_fc, b_fc, out_pred);
}